// round 12
// baseline (speedup 1.0000x reference)
#include <cuda_runtime.h>
#include <cuda_fp16.h>

#define F_NODES 16384
#define DEG 8
#define E (F_NODES * DEG)   // 131072
#define B 64
#define H 16
#define LAYERS 10

#define NPB 8               // nodes per block = warps per block

typedef unsigned long long u64;

// x0 kept fp32 only for the FINAL layer residual (exact); all steady-state
// traffic is fp16: x0H residual + fp16 ping-pong. Working set ~69MB << L2.
__device__ float  g_x0T[(size_t)E * B];
__device__ __half g_x0H[(size_t)E * B];
__device__ __half g_hA [(size_t)E * B];
__device__ __half g_hB [(size_t)E * B];

__device__ __forceinline__ u64 pack2(float lo, float hi) {
    u64 r; asm("mov.b64 %0, {%1, %2};" : "=l"(r) : "f"(lo), "f"(hi)); return r;
}
__device__ __forceinline__ void unpack2(u64 v, float& lo, float& hi) {
    asm("mov.b64 {%0, %1}, %2;" : "=f"(lo), "=f"(hi) : "l"(v));
}
__device__ __forceinline__ void fma2(u64& d, u64 a, u64 b, u64 c) {
    asm("fma.rn.f32x2 %0, %1, %2, %3;" : "=l"(d) : "l"(a), "l"(b), "l"(c));
}
__device__ __forceinline__ u64 add2(u64 a, u64 b) {
    u64 r; asm("add.rn.f32x2 %0, %1, %2;" : "=l"(r) : "l"(a), "l"(b)); return r;
}
// ELU via select: FMUL+MUFU+FADD+FSETP+FSEL, no branch.
__device__ __forceinline__ float elu1(float x) {
    float e = __expf(x) - 1.0f;
    return x > 0.0f ? x : e;
}

// Per-node smem weights, fully pre-splatted/pre-packed at staging time so the
// j-loop does zero weight-format ALU work.
struct __align__(16) NodeW {
    u64 sb1[16];      // b1 splats (bj, bj)
    u64 sb2p[4];      // b2 raw dim-pairs (b2[2k], b2[2k+1])
    u64 w1s[128];     // splat(W1[j*8+d])
    u64 w2p[64];      // w2p[j*4+k] = (W2[2k][j], W2[2k+1][j])
    u64 pad[2];
};

// (B, E) row-major -> (E, B) fp32 (final-layer residual) + fp16 (everything else)
__global__ void k_transpose_in(const float* __restrict__ in,
                               float* __restrict__ outf, __half* __restrict__ outh) {
    __shared__ float t[32][33];
    int e0 = blockIdx.x * 32, b0 = blockIdx.y * 32;
    int tx = threadIdx.x, ty = threadIdx.y;
    t[ty][tx] = in[(size_t)(b0 + ty) * E + e0 + tx];
    __syncthreads();
    float v = t[tx][ty];
    size_t o = (size_t)(e0 + ty) * B + b0 + tx;
    outf[o] = v;
    outh[o] = __float2half(v);
}

// One GSNN layer in (E, B) space. ONE WARP PER NODE, 2 batch elems per lane.
// Math fp32; x read/written fp16. Non-final: residual from fp16 x0H.
// Final: residual from fp32 x0T, fp32 (B,E) output via register transpose.
// No block barrier: each warp stages and consumes only its own node's weights.
__global__ __launch_bounds__(NPB * 32)
void layer_kernel(const __half* __restrict__ src, __half* __restrict__ dsth,
                  float* __restrict__ dstf,
                  const float* __restrict__ W1, const float* __restrict__ b1,
                  const float* __restrict__ W2, const float* __restrict__ b2,
                  const int* __restrict__ in_ixs,
                  const __half* __restrict__ x0H, const float* __restrict__ x0T,
                  int final_flag) {
    __shared__ NodeW sw[NPB];
    const int lane = threadIdx.x & 31;   // batch pair: handles b = 2*lane, 2*lane+1
    const int nl   = threadIdx.x >> 5;   // node within block (= warp id)
    const int node = blockIdx.x * NPB + nl;
    NodeW& nw = sw[nl];

    // Issue gathers first (longest latency); 4B (1 batch-pair) per lane per column.
    const int4 c0 = ((const int4*)(in_ixs + (size_t)node * 8))[0];
    const int4 c1 = ((const int4*)(in_ixs + (size_t)node * 8))[1];
    const int cols[8] = {c0.x, c0.y, c0.z, c0.w, c1.x, c1.y, c1.z, c1.w};
    unsigned gh[8];
#pragma unroll
    for (int d = 0; d < 8; d++)
        gh[d] = *(const unsigned*)(src + (((size_t)cols[d]) << 6) + (lane << 1));

    // Stage weights (warp-local; pre-splat W1, pre-pack W2 dim-pairs).
    {
        // W1: lane stages floats [4*lane, 4*lane+4) as 4 splat u64s.
        const float4 a = ((const float4*)(W1 + (size_t)node * 128))[lane];
        ulonglong2* w1v = (ulonglong2*)(nw.w1s + lane * 4);
        w1v[0] = make_ulonglong2(pack2(a.x, a.x), pack2(a.y, a.y));
        w1v[1] = make_ulonglong2(pack2(a.z, a.z), pack2(a.w, a.w));
        // W2: lane handles column j = lane>>1, dims 4*(lane&1)..+3.
        const int j  = lane >> 1;
        const int dm = (lane & 1) * 4;
        const float* gW2 = W2 + (size_t)node * 128;   // [d][j]
        float w0 = gW2[(dm + 0) * 16 + j];
        float w1_ = gW2[(dm + 1) * 16 + j];
        float w2_ = gW2[(dm + 2) * 16 + j];
        float w3 = gW2[(dm + 3) * 16 + j];
        *(ulonglong2*)(nw.w2p + j * 4 + dm / 2) =
            make_ulonglong2(pack2(w0, w1_), pack2(w2_, w3));
        if (lane < 16) {
            float bj = b1[(size_t)node * 16 + lane];
            nw.sb1[lane] = pack2(bj, bj);
        } else if (lane < 20) {
            int k = lane - 16;
            nw.sb2p[k] = *(const u64*)(b2 + (size_t)node * 8 + 2 * k);
        }
    }
    __syncwarp();

    // Gathered halves -> packed fp32 batch-pair.
    u64 g[8];
#pragma unroll
    for (int d = 0; d < 8; d++) {
        float2 f = __half22float2(*(__half2*)&gh[d]);
        g[d] = pack2(f.x, f.y);
    }

    // Accumulators o[k][b]: lanes = out-dim pair (2k, 2k+1), b = batch in pair.
    u64 o[4][2];
#pragma unroll
    for (int k = 0; k < 4; k++) {
        o[k][0] = nw.sb2p[k];
        o[k][1] = o[k][0];
    }

#pragma unroll
    for (int j = 0; j < 16; j++) {
        // W1 splats: 4x LDS.128 (8 u64, zero ALU).
        const ulonglong2 sA = ((const ulonglong2*)(nw.w1s + j * 8))[0];
        const ulonglong2 sB = ((const ulonglong2*)(nw.w1s + j * 8))[1];
        const ulonglong2 sC = ((const ulonglong2*)(nw.w1s + j * 8))[2];
        const ulonglong2 sD = ((const ulonglong2*)(nw.w1s + j * 8))[3];

        // Two 4-deep chains, then combine.
        u64 pA = nw.sb1[j], pB = 0;
        fma2(pA, g[0], sA.x, pA); fma2(pB, g[4], sC.x, pB);
        fma2(pA, g[1], sA.y, pA); fma2(pB, g[5], sC.y, pB);
        fma2(pA, g[2], sB.x, pA); fma2(pB, g[6], sD.x, pB);
        fma2(pA, g[3], sB.y, pA); fma2(pB, g[7], sD.y, pB);
        const u64 a0 = add2(pA, pB);

        float h0, h1;
        unpack2(a0, h0, h1);
        h0 = elu1(h0); h1 = elu1(h1);
        const u64 hs0 = pack2(h0, h0), hs1 = pack2(h1, h1);

        // W2 dim-pairs: 2x LDS.128 (4 u64, zero ALU).
        const ulonglong2 wA = ((const ulonglong2*)(nw.w2p + j * 4))[0];
        const ulonglong2 wB = ((const ulonglong2*)(nw.w2p + j * 4))[1];
        fma2(o[0][0], hs0, wA.x, o[0][0]); fma2(o[0][1], hs1, wA.x, o[0][1]);
        fma2(o[1][0], hs0, wA.y, o[1][0]); fma2(o[1][1], hs1, wA.y, o[1][1]);
        fma2(o[2][0], hs0, wB.x, o[2][0]); fma2(o[2][1], hs1, wB.x, o[2][1]);
        fma2(o[3][0], hs0, wB.y, o[3][0]); fma2(o[3][1], hs1, wB.y, o[3][1]);
    }

    // Extract out[d][b] scalars.
    float ov[8][2];
#pragma unroll
    for (int k = 0; k < 4; k++) {
#pragma unroll
        for (int b = 0; b < 2; b++) {
            float lo, hi;
            unpack2(o[k][b], lo, hi);
            ov[2 * k][b]     = lo;
            ov[2 * k + 1][b] = hi;
        }
    }

    if (!final_flag) {
        // fp16 residual + fp16 store; lane writes its 4B batch-pair per column.
#pragma unroll
        for (int d = 0; d < 8; d++) {
            const size_t col = (size_t)node * 8 + d;
            const unsigned rh = *(const unsigned*)(x0H + (col << 6) + (lane << 1));
            const float2 r = __half22float2(*(__half2*)&rh);
            __half2 hv = __floats2half2_rn(ov[d][0] + r.x, ov[d][1] + r.y);
            *(unsigned*)(dsth + (col << 6) + (lane << 1)) = *(unsigned*)&hv;
        }
    } else {
        // Final: exact fp32 residual + register transpose + fp32 (B,E) store.
        float2 r[8];
#pragma unroll
        for (int d = 0; d < 8; d++)
            r[d] = *(const float2*)(x0T + (((size_t)node * 8 + d) << 6) + (lane << 1));
#pragma unroll
        for (int rr = 0; rr < 2; rr++) {
            float* p = dstf + (size_t)(2 * lane + rr) * E + (size_t)node * 8;
            const float4 v0 = make_float4(ov[0][rr] + (rr ? r[0].y : r[0].x),
                                          ov[1][rr] + (rr ? r[1].y : r[1].x),
                                          ov[2][rr] + (rr ? r[2].y : r[2].x),
                                          ov[3][rr] + (rr ? r[3].y : r[3].x));
            const float4 v1 = make_float4(ov[4][rr] + (rr ? r[4].y : r[4].x),
                                          ov[5][rr] + (rr ? r[5].y : r[5].x),
                                          ov[6][rr] + (rr ? r[6].y : r[6].x),
                                          ov[7][rr] + (rr ? r[7].y : r[7].x));
            *(float4*)(p)     = v0;
            *(float4*)(p + 4) = v1;
        }
    }
}

extern "C" void kernel_launch(void* const* d_in, const int* in_sizes, int n_in,
                              void* d_out, int out_size) {
    const float* x0     = (const float*)d_in[0];
    const float* W1     = (const float*)d_in[1];
    const float* b1     = (const float*)d_in[2];
    const float* W2     = (const float*)d_in[3];
    const float* b2     = (const float*)d_in[4];
    const int*   in_ixs = (const int*)d_in[5];
    float* out = (float*)d_out;

    float *x0T;
    __half *x0H, *hA, *hB;
    cudaGetSymbolAddress((void**)&x0T, g_x0T);
    cudaGetSymbolAddress((void**)&x0H, g_x0H);
    cudaGetSymbolAddress((void**)&hA,  g_hA);
    cudaGetSymbolAddress((void**)&hB,  g_hB);

    k_transpose_in<<<dim3(E / 32, B / 32), dim3(32, 32)>>>(x0, x0T, x0H);

    const __half* src = x0H;
    __half* bufs[2] = {hA, hB};
    for (int L = 0; L < LAYERS; L++) {
        const int fin = (L == LAYERS - 1);
        __half* dh = fin ? nullptr : bufs[L & 1];
        layer_kernel<<<F_NODES / NPB, NPB * 32>>>(src, dh, fin ? out : nullptr,
                                                  W1, b1, W2, b2, in_ixs,
                                                  x0H, x0T, fin);
        src = dh;
    }
}

// round 14
// speedup vs baseline: 1.0464x; 1.0464x over previous
#include <cuda_runtime.h>
#include <cuda_fp16.h>

#define F_NODES 16384
#define DEG 8
#define E (F_NODES * DEG)   // 131072
#define B 64
#define H 16
#define LAYERS 10

#define NPB 8               // nodes per block = warps per block

typedef unsigned long long u64;
typedef unsigned int u32;
typedef unsigned short u16;

// x0 fp32 for the exact final-layer residual; steady-state x traffic is fp16.
__device__ float  g_x0T[(size_t)E * B];
__device__ __half g_x0H[(size_t)E * B];
__device__ __half g_hA [(size_t)E * B];
__device__ __half g_hB [(size_t)E * B];
// fp16 hi/lo weight split (W ~= Wh + Wl exactly to ~2^-22), built once per run.
__device__ __half g_w1h[(size_t)F_NODES * 128];
__device__ __half g_w1l[(size_t)F_NODES * 128];
__device__ __half g_w2h[(size_t)F_NODES * 128];
__device__ __half g_w2l[(size_t)F_NODES * 128];

__device__ __forceinline__ float elu1(float x) {
    float e = __expf(x) - 1.0f;
    return x > 0.0f ? x : e;
}
// pack two f32 -> f16x2, lo in low half.
__device__ __forceinline__ u32 cvt2h(float lo, float hi) {
    u32 r;
    asm("cvt.rn.f16x2.f32 %0, %1, %2;" : "=r"(r) : "f"(hi), "f"(lo));
    return r;
}
__device__ __forceinline__ u32 packh(u16 lo, u16 hi) {
    u32 r;
    asm("mov.b32 %0, {%1, %2};" : "=r"(r) : "h"(lo), "h"(hi));
    return r;
}
__device__ __forceinline__ void mma_k8(float c[4], u32 a0, u32 a1, u32 b0) {
    asm("mma.sync.aligned.m16n8k8.row.col.f32.f16.f16.f32 "
        "{%0,%1,%2,%3}, {%4,%5}, {%6}, {%0,%1,%2,%3};"
        : "+f"(c[0]), "+f"(c[1]), "+f"(c[2]), "+f"(c[3])
        : "r"(a0), "r"(a1), "r"(b0));
}
__device__ __forceinline__ void mma_k16(float c[4], const u32 a[4], u32 b0, u32 b1) {
    asm("mma.sync.aligned.m16n8k16.row.col.f32.f16.f16.f32 "
        "{%0,%1,%2,%3}, {%4,%5,%6,%7}, {%8,%9}, {%0,%1,%2,%3};"
        : "+f"(c[0]), "+f"(c[1]), "+f"(c[2]), "+f"(c[3])
        : "r"(a[0]), "r"(a[1]), "r"(a[2]), "r"(a[3]), "r"(b0), "r"(b1));
}

// Per-node smem: weights only (gather goes straight to fragments).
struct __align__(16) NodeS {
    __half w1h[128];   // [j*8 + d]
    __half w1l[128];
    __half w2h[160];   // [d*20 + j] (rows padded to 40B)
    __half w2l[160];
    float  b1f[16];
    float  b2f[8];
};

// One-time fp16 hi/lo weight split.
__global__ void k_prep_weights(const float* __restrict__ W1, const float* __restrict__ W2) {
    size_t i = (size_t)blockIdx.x * blockDim.x + threadIdx.x;  // < F_NODES*128
    float w1 = W1[i];
    __half h1 = __float2half_rn(w1);
    g_w1h[i] = h1;
    g_w1l[i] = __float2half_rn(w1 - __half2float(h1));
    float w2 = W2[i];
    __half h2 = __float2half_rn(w2);
    g_w2h[i] = h2;
    g_w2l[i] = __float2half_rn(w2 - __half2float(h2));
}

// (B, E) row-major -> (E, B) fp32 + fp16
__global__ void k_transpose_in(const float* __restrict__ in,
                               float* __restrict__ outf, __half* __restrict__ outh) {
    __shared__ float t[32][33];
    int e0 = blockIdx.x * 32, b0 = blockIdx.y * 32;
    int tx = threadIdx.x, ty = threadIdx.y;
    t[ty][tx] = in[(size_t)(b0 + ty) * E + e0 + tx];
    __syncthreads();
    float v = t[tx][ty];
    size_t o = (size_t)(e0 + ty) * B + b0 + tx;
    outf[o] = v;
    outh[o] = __float2half(v);
}

// One GSNN layer: ONE WARP PER NODE, tensor-core MMAs.
// GEMM1: C1[64,16] = G[64,8] x W1^T  (2x mma.k8 per tile, W hi/lo)
// GEMM2: C2[64,8]  = ELU(C1+b1)[64,16] x W2^T (2x mma.k16 per m-tile)
__global__ __launch_bounds__(NPB * 32)
void layer_kernel(const __half* __restrict__ src, __half* __restrict__ dsth,
                  float* __restrict__ dstf,
                  const float* __restrict__ b1, const float* __restrict__ b2,
                  const int* __restrict__ in_ixs,
                  const __half* __restrict__ x0H, const float* __restrict__ x0T,
                  int final_flag) {
    __shared__ NodeS sw[NPB];
    const int lane = threadIdx.x & 31;
    const int nl   = threadIdx.x >> 5;
    const int node = blockIdx.x * NPB + nl;
    const int t    = lane & 3;       // threadID in group
    const int g    = lane >> 2;      // group id
    NodeS& nw = sw[nl];

    // Stage weights (flat copies; w2 re-strided to padded rows).
    {
        const size_t wb = (size_t)node * 128;
        *(u64*)(nw.w1h + 4 * lane) = *(const u64*)(g_w1h + wb + 4 * lane);
        *(u64*)(nw.w1l + 4 * lane) = *(const u64*)(g_w1l + wb + 4 * lane);
        const int d  = lane >> 2;          // 4-half chunk: d = l/4, j0 = (l%4)*4
        const int j0 = (lane & 3) * 4;
        *(u64*)(nw.w2h + d * 20 + j0) = *(const u64*)(g_w2h + wb + d * 16 + j0);
        *(u64*)(nw.w2l + d * 20 + j0) = *(const u64*)(g_w2l + wb + d * 16 + j0);
        if (lane < 16) nw.b1f[lane] = b1[(size_t)node * 16 + lane];
        else if (lane < 24) nw.b2f[lane - 16] = b2[(size_t)node * 8 + (lane - 16)];
    }

    // Gather columns for this node.
    const int4 ci0 = ((const int4*)(in_ixs + (size_t)node * 8))[0];
    const int4 ci1 = ((const int4*)(in_ixs + (size_t)node * 8))[1];
    const int cols[8] = {ci0.x, ci0.y, ci0.z, ci0.w, ci1.x, ci1.y, ci1.z, ci1.w};
    const __half* colA = src + (size_t)cols[2 * t] * B;       // col d = 2t
    const __half* colB = src + (size_t)cols[2 * t + 1] * B;   // col d = 2t+1

    // A fragments for GEMM1 (m16n8k8): per m-tile mi, rows b = 16mi+g, +8.
    u32 a1f[4][2];
#pragma unroll
    for (int mi = 0; mi < 4; mi++) {
        const int b0r = 16 * mi + g;
        u16 x0 = *(const u16*)(colA + b0r);
        u16 x1 = *(const u16*)(colB + b0r);
        u16 x2 = *(const u16*)(colA + b0r + 8);
        u16 x3 = *(const u16*)(colB + b0r + 8);
        a1f[mi][0] = packh(x0, x1);
        a1f[mi][1] = packh(x2, x3);
    }

    __syncwarp();

    // B fragments GEMM1: row j = 8ni+g, halves d = 2t, 2t+1.
    u32 b1h[2], b1l[2];
#pragma unroll
    for (int ni = 0; ni < 2; ni++) {
        b1h[ni] = *(const u32*)((const char*)nw.w1h + (8 * ni + g) * 16 + 4 * t);
        b1l[ni] = *(const u32*)((const char*)nw.w1l + (8 * ni + g) * 16 + 4 * t);
    }

    // GEMM1 with bias-initialized accumulators.
    float c1[4][2][4];
#pragma unroll
    for (int ni = 0; ni < 2; ni++) {
        const float2 bb = *(const float2*)(nw.b1f + 8 * ni + 2 * t);
#pragma unroll
        for (int mi = 0; mi < 4; mi++) {
            c1[mi][ni][0] = bb.x; c1[mi][ni][1] = bb.y;
            c1[mi][ni][2] = bb.x; c1[mi][ni][3] = bb.y;
        }
    }
#pragma unroll
    for (int mi = 0; mi < 4; mi++) {
#pragma unroll
        for (int ni = 0; ni < 2; ni++) {
            mma_k8(c1[mi][ni], a1f[mi][0], a1f[mi][1], b1h[ni]);
            mma_k8(c1[mi][ni], a1f[mi][0], a1f[mi][1], b1l[ni]);
        }
    }

    // ELU + pack into GEMM2 A fragments (C1 layout == A(k16) layout).
    u32 a2f[4][4];
#pragma unroll
    for (int mi = 0; mi < 4; mi++) {
        a2f[mi][0] = cvt2h(elu1(c1[mi][0][0]), elu1(c1[mi][0][1]));
        a2f[mi][1] = cvt2h(elu1(c1[mi][0][2]), elu1(c1[mi][0][3]));
        a2f[mi][2] = cvt2h(elu1(c1[mi][1][0]), elu1(c1[mi][1][1]));
        a2f[mi][3] = cvt2h(elu1(c1[mi][1][2]), elu1(c1[mi][1][3]));
    }

    // B fragments GEMM2: B(r=j, c=d) = W2[d][j]; row d = g, halves j = 2t(+8).
    const u32 b2h0 = *(const u32*)((const char*)nw.w2h + g * 40 + 4 * t);
    const u32 b2h1 = *(const u32*)((const char*)nw.w2h + g * 40 + 4 * t + 16);
    const u32 b2l0 = *(const u32*)((const char*)nw.w2l + g * 40 + 4 * t);
    const u32 b2l1 = *(const u32*)((const char*)nw.w2l + g * 40 + 4 * t + 16);

    // GEMM2 with b2-initialized accumulators.
    float c2[4][4];
    {
        const float2 bb2 = *(const float2*)(nw.b2f + 2 * t);
#pragma unroll
        for (int mi = 0; mi < 4; mi++) {
            c2[mi][0] = bb2.x; c2[mi][1] = bb2.y;
            c2[mi][2] = bb2.x; c2[mi][3] = bb2.y;
        }
    }
#pragma unroll
    for (int mi = 0; mi < 4; mi++) {
        mma_k16(c2[mi], a2f[mi], b2h0, b2h1);
        mma_k16(c2[mi], a2f[mi], b2l0, b2l1);
    }

    // Residual + store. C2 element e: row = g + (e>=2)*8, col d = 2t + (e&1).
    if (!final_flag) {
#pragma unroll
        for (int mi = 0; mi < 4; mi++) {
#pragma unroll
            for (int e = 0; e < 4; e++) {
                const int bb = 16 * mi + g + ((e >> 1) << 3);
                const int d  = 2 * t + (e & 1);
                const size_t off = ((size_t)node * 8 + d) * B + bb;
                float rv = __half2float(x0H[off]);
                dsth[off] = __float2half_rn(c2[mi][e] + rv);
            }
        }
    } else {
#pragma unroll
        for (int mi = 0; mi < 4; mi++) {
#pragma unroll
            for (int e = 0; e < 4; e++) {
                const int bb = 16 * mi + g + ((e >> 1) << 3);
                const int d  = 2 * t + (e & 1);
                const float rv = x0T[((size_t)node * 8 + d) * B + bb];
                dstf[(size_t)bb * E + (size_t)node * 8 + d] = c2[mi][e] + rv;
            }
        }
    }
}

extern "C" void kernel_launch(void* const* d_in, const int* in_sizes, int n_in,
                              void* d_out, int out_size) {
    const float* x0     = (const float*)d_in[0];
    const float* W1     = (const float*)d_in[1];
    const float* b1     = (const float*)d_in[2];
    const float* W2     = (const float*)d_in[3];
    const float* b2     = (const float*)d_in[4];
    const int*   in_ixs = (const int*)d_in[5];
    float* out = (float*)d_out;

    float *x0T;
    __half *x0H, *hA, *hB;
    cudaGetSymbolAddress((void**)&x0T, g_x0T);
    cudaGetSymbolAddress((void**)&x0H, g_x0H);
    cudaGetSymbolAddress((void**)&hA,  g_hA);
    cudaGetSymbolAddress((void**)&hB,  g_hB);

    k_prep_weights<<<(F_NODES * 128) / 256, 256>>>(W1, W2);
    k_transpose_in<<<dim3(E / 32, B / 32), dim3(32, 32)>>>(x0, x0T, x0H);

    const __half* src = x0H;
    __half* bufs[2] = {hA, hB};
    for (int L = 0; L < LAYERS; L++) {
        const int fin = (L == LAYERS - 1);
        __half* dh = fin ? nullptr : bufs[L & 1];
        layer_kernel<<<F_NODES / NPB, NPB * 32>>>(src, dh, fin ? out : nullptr,
                                                  b1, b2, in_ixs, x0H, x0T, fin);
        src = dh;
    }
}

// round 15
// speedup vs baseline: 1.3757x; 1.3147x over previous
#include <cuda_runtime.h>
#include <cuda_fp16.h>

#define F_NODES 16384
#define DEG 8
#define E (F_NODES * DEG)   // 131072
#define B 64
#define H 16
#define LAYERS 10

#define NPB 8               // nodes per block = warps per block
#define TS 72               // tile row stride in halves (144B: 16B-aligned, bank-spread)

typedef unsigned long long u64;
typedef unsigned int u32;
typedef unsigned short u16;

// x0 fp32 for the exact final-layer residual; steady-state x traffic is fp16.
__device__ float  g_x0T[(size_t)E * B];
__device__ __half g_x0H[(size_t)E * B];
__device__ __half g_hA [(size_t)E * B];
__device__ __half g_hB [(size_t)E * B];
// fp16 hi/lo weight split (W ~= Wh + Wl to ~2^-22), built once per run.
__device__ __half g_w1h[(size_t)F_NODES * 128];
__device__ __half g_w1l[(size_t)F_NODES * 128];
__device__ __half g_w2h[(size_t)F_NODES * 128];
__device__ __half g_w2l[(size_t)F_NODES * 128];

__device__ __forceinline__ float elu1(float x) {
    float e = __expf(x) - 1.0f;
    return x > 0.0f ? x : e;
}
// pack two f32 -> f16x2, lo in low half.
__device__ __forceinline__ u32 cvt2h(float lo, float hi) {
    u32 r;
    asm("cvt.rn.f16x2.f32 %0, %1, %2;" : "=r"(r) : "f"(hi), "f"(lo));
    return r;
}
__device__ __forceinline__ void mma_k8(float c[4], u32 a0, u32 a1, u32 b0) {
    asm("mma.sync.aligned.m16n8k8.row.col.f32.f16.f16.f32 "
        "{%0,%1,%2,%3}, {%4,%5}, {%6}, {%0,%1,%2,%3};"
        : "+f"(c[0]), "+f"(c[1]), "+f"(c[2]), "+f"(c[3])
        : "r"(a0), "r"(a1), "r"(b0));
}
__device__ __forceinline__ void mma_k16(float c[4], const u32 a[4], u32 b0, u32 b1) {
    asm("mma.sync.aligned.m16n8k16.row.col.f32.f16.f16.f32 "
        "{%0,%1,%2,%3}, {%4,%5,%6,%7}, {%8,%9}, {%0,%1,%2,%3};"
        : "+f"(c[0]), "+f"(c[1]), "+f"(c[2]), "+f"(c[3])
        : "r"(a[0]), "r"(a[1]), "r"(a[2]), "r"(a[3]), "r"(b0), "r"(b1));
}
__device__ __forceinline__ void ldsm4t(u32& r0, u32& r1, u32& r2, u32& r3, u32 addr) {
    asm volatile("ldmatrix.sync.aligned.m8n8.x4.trans.shared.b16 {%0,%1,%2,%3}, [%4];"
                 : "=r"(r0), "=r"(r1), "=r"(r2), "=r"(r3) : "r"(addr));
}
__device__ __forceinline__ void stsm4t(u32 addr, u32 r0, u32 r1, u32 r2, u32 r3) {
    asm volatile("stmatrix.sync.aligned.m8n8.x4.trans.shared.b16 [%0], {%1,%2,%3,%4};"
                 :: "r"(addr), "r"(r0), "r"(r1), "r"(r2), "r"(r3) : "memory");
}

// Per-node smem.
struct __align__(16) NodeS {
    __half w1h[128];    // [j*8 + d]
    __half w1l[128];
    __half w2h[160];    // [d*20 + j] (rows padded to 40B)
    __half w2l[160];
    float  b1f[16];
    float  b2f[8];
    __half tile[8 * TS]; // G^T staging in, C2^T staging out (rows d, stride 144B)
};

// One-time fp16 hi/lo weight split.
__global__ void k_prep_weights(const float* __restrict__ W1, const float* __restrict__ W2) {
    size_t i = (size_t)blockIdx.x * blockDim.x + threadIdx.x;
    float w1 = W1[i];
    __half h1 = __float2half_rn(w1);
    g_w1h[i] = h1;
    g_w1l[i] = __float2half_rn(w1 - __half2float(h1));
    float w2 = W2[i];
    __half h2 = __float2half_rn(w2);
    g_w2h[i] = h2;
    g_w2l[i] = __float2half_rn(w2 - __half2float(h2));
}

// (B, E) row-major -> (E, B) fp32 + fp16
__global__ void k_transpose_in(const float* __restrict__ in,
                               float* __restrict__ outf, __half* __restrict__ outh) {
    __shared__ float t[32][33];
    int e0 = blockIdx.x * 32, b0 = blockIdx.y * 32;
    int tx = threadIdx.x, ty = threadIdx.y;
    t[ty][tx] = in[(size_t)(b0 + ty) * E + e0 + tx];
    __syncthreads();
    float v = t[tx][ty];
    size_t o = (size_t)(e0 + ty) * B + b0 + tx;
    outf[o] = v;
    outh[o] = __float2half(v);
}

// One GSNN layer: ONE WARP PER NODE, tensor-core MMAs, ldmatrix/stmatrix I/O.
__global__ __launch_bounds__(NPB * 32)
void layer_kernel(const __half* __restrict__ src, __half* __restrict__ dsth,
                  float* __restrict__ dstf,
                  const float* __restrict__ b1, const float* __restrict__ b2,
                  const int* __restrict__ in_ixs,
                  const __half* __restrict__ x0H, const float* __restrict__ x0T,
                  int final_flag) {
    __shared__ NodeS sw[NPB];
    const int lane = threadIdx.x & 31;
    const int nl   = threadIdx.x >> 5;
    const int node = blockIdx.x * NPB + nl;
    const int t    = lane & 3;       // colpair within fragment group
    const int g    = lane >> 2;      // fragment row group
    NodeS& nw = sw[nl];

    // Stage weights.
    {
        const size_t wb = (size_t)node * 128;
        *(u64*)(nw.w1h + 4 * lane) = *(const u64*)(g_w1h + wb + 4 * lane);
        *(u64*)(nw.w1l + 4 * lane) = *(const u64*)(g_w1l + wb + 4 * lane);
        const int d  = lane >> 2;
        const int j0 = (lane & 3) * 4;
        *(u64*)(nw.w2h + d * 20 + j0) = *(const u64*)(g_w2h + wb + d * 16 + j0);
        *(u64*)(nw.w2l + d * 20 + j0) = *(const u64*)(g_w2l + wb + d * 16 + j0);
        if (lane < 16) nw.b1f[lane] = b1[(size_t)node * 16 + lane];
        else if (lane < 24) nw.b2f[lane - 16] = b2[(size_t)node * 8 + (lane - 16)];
    }

    // Gather columns -> smem tile G^T[d][b] (coalesced u64 loads/stores).
    const int4 ci0 = ((const int4*)(in_ixs + (size_t)node * 8))[0];
    const int4 ci1 = ((const int4*)(in_ixs + (size_t)node * 8))[1];
    const int cols[8] = {ci0.x, ci0.y, ci0.z, ci0.w, ci1.x, ci1.y, ci1.z, ci1.w};
    const int hw = lane >> 4;      // half-warp id
    const int bo = lane & 15;      // 8B chunk within column
#pragma unroll
    for (int p = 0; p < 4; p++) {
        const int d = 2 * p + hw;
        *(u64*)(nw.tile + d * TS + bo * 4) =
            *(const u64*)(src + (size_t)cols[d] * B + bo * 4);
    }
    __syncwarp();

    // A fragments for GEMM1 via 2x ldmatrix.x4.trans.
    const u32 smb = (u32)__cvta_generic_to_shared(nw.tile);
    const u32 la  = smb + (lane & 7) * (TS * 2) + (lane >> 3) * 16;
    u32 a1f[4][2];
    ldsm4t(a1f[0][0], a1f[0][1], a1f[1][0], a1f[1][1], la);
    ldsm4t(a1f[2][0], a1f[2][1], a1f[3][0], a1f[3][1], la + 64);

    // B fragments GEMM1: row j = 8ni+g, halves d = 2t, 2t+1.
    u32 b1h[2], b1l[2];
#pragma unroll
    for (int ni = 0; ni < 2; ni++) {
        b1h[ni] = *(const u32*)((const char*)nw.w1h + (8 * ni + g) * 16 + 4 * t);
        b1l[ni] = *(const u32*)((const char*)nw.w1l + (8 * ni + g) * 16 + 4 * t);
    }

    // GEMM1 with bias-initialized accumulators (W hi + lo).
    float c1[4][2][4];
#pragma unroll
    for (int ni = 0; ni < 2; ni++) {
        const float2 bb = *(const float2*)(nw.b1f + 8 * ni + 2 * t);
#pragma unroll
        for (int mi = 0; mi < 4; mi++) {
            c1[mi][ni][0] = bb.x; c1[mi][ni][1] = bb.y;
            c1[mi][ni][2] = bb.x; c1[mi][ni][3] = bb.y;
        }
    }
#pragma unroll
    for (int mi = 0; mi < 4; mi++) {
#pragma unroll
        for (int ni = 0; ni < 2; ni++) {
            mma_k8(c1[mi][ni], a1f[mi][0], a1f[mi][1], b1h[ni]);
            mma_k8(c1[mi][ni], a1f[mi][0], a1f[mi][1], b1l[ni]);
        }
    }

    // ELU + pack into GEMM2 A fragments (C layout == A(k16) layout).
    u32 a2f[4][4];
#pragma unroll
    for (int mi = 0; mi < 4; mi++) {
        a2f[mi][0] = cvt2h(elu1(c1[mi][0][0]), elu1(c1[mi][0][1]));
        a2f[mi][1] = cvt2h(elu1(c1[mi][0][2]), elu1(c1[mi][0][3]));
        a2f[mi][2] = cvt2h(elu1(c1[mi][1][0]), elu1(c1[mi][1][1]));
        a2f[mi][3] = cvt2h(elu1(c1[mi][1][2]), elu1(c1[mi][1][3]));
    }

    // B fragments GEMM2: B(r=j, c=d) = W2[d][j]; row d = g, halves j = 2t(+8).
    const u32 b2h0 = *(const u32*)((const char*)nw.w2h + g * 40 + 4 * t);
    const u32 b2h1 = *(const u32*)((const char*)nw.w2h + g * 40 + 4 * t + 16);
    const u32 b2l0 = *(const u32*)((const char*)nw.w2l + g * 40 + 4 * t);
    const u32 b2l1 = *(const u32*)((const char*)nw.w2l + g * 40 + 4 * t + 16);

    // GEMM2 with b2-initialized accumulators.
    float c2[4][4];
    {
        const float2 bb2 = *(const float2*)(nw.b2f + 2 * t);
#pragma unroll
        for (int mi = 0; mi < 4; mi++) {
            c2[mi][0] = bb2.x; c2[mi][1] = bb2.y;
            c2[mi][2] = bb2.x; c2[mi][3] = bb2.y;
        }
    }
#pragma unroll
    for (int mi = 0; mi < 4; mi++) {
        mma_k16(c2[mi], a2f[mi], b2h0, b2h1);
        mma_k16(c2[mi], a2f[mi], b2l0, b2l1);
    }

    if (!final_flag) {
        // C2 -> fp16 fragments -> stmatrix into tile (as C2^T[d][b]) ->
        // coalesced readback + fp16 residual + coalesced store.
        u32 m[8];
#pragma unroll
        for (int mi = 0; mi < 4; mi++) {
            m[2 * mi]     = cvt2h(c2[mi][0], c2[mi][1]);
            m[2 * mi + 1] = cvt2h(c2[mi][2], c2[mi][3]);
        }
        __syncwarp();
        stsm4t(la, m[0], m[1], m[2], m[3]);
        stsm4t(la + 64, m[4], m[5], m[6], m[7]);
        __syncwarp();
#pragma unroll
        for (int p = 0; p < 4; p++) {
            const int d = 2 * p + hw;
            const u64 v = *(const u64*)(nw.tile + d * TS + bo * 4);
            const size_t off = ((size_t)node * 8 + d) * B + bo * 4;
            const u64 r = *(const u64*)(x0H + off);
            __half2 o0 = __hadd2(((const __half2*)&v)[0], ((const __half2*)&r)[0]);
            __half2 o1 = __hadd2(((const __half2*)&v)[1], ((const __half2*)&r)[1]);
            u64 ov;
            ((__half2*)&ov)[0] = o0;
            ((__half2*)&ov)[1] = o1;
            *(u64*)(dsth + off) = ov;
        }
    } else {
        // Final layer: exact fp32 residual, fp32 (B,E) output (register scatter).
#pragma unroll
        for (int mi = 0; mi < 4; mi++) {
#pragma unroll
            for (int e = 0; e < 4; e++) {
                const int bb = 16 * mi + g + ((e >> 1) << 3);
                const int d  = 2 * t + (e & 1);
                const float rv = x0T[((size_t)node * 8 + d) * B + bb];
                dstf[(size_t)bb * E + (size_t)node * 8 + d] = c2[mi][e] + rv;
            }
        }
    }
}

extern "C" void kernel_launch(void* const* d_in, const int* in_sizes, int n_in,
                              void* d_out, int out_size) {
    const float* x0     = (const float*)d_in[0];
    const float* W1     = (const float*)d_in[1];
    const float* b1     = (const float*)d_in[2];
    const float* W2     = (const float*)d_in[3];
    const float* b2     = (const float*)d_in[4];
    const int*   in_ixs = (const int*)d_in[5];
    float* out = (float*)d_out;

    float *x0T;
    __half *x0H, *hA, *hB;
    cudaGetSymbolAddress((void**)&x0T, g_x0T);
    cudaGetSymbolAddress((void**)&x0H, g_x0H);
    cudaGetSymbolAddress((void**)&hA,  g_hA);
    cudaGetSymbolAddress((void**)&hB,  g_hB);

    k_prep_weights<<<(F_NODES * 128) / 256, 256>>>(W1, W2);
    k_transpose_in<<<dim3(E / 32, B / 32), dim3(32, 32)>>>(x0, x0T, x0H);

    const __half* src = x0H;
    __half* bufs[2] = {hA, hB};
    for (int L = 0; L < LAYERS; L++) {
        const int fin = (L == LAYERS - 1);
        __half* dh = fin ? nullptr : bufs[L & 1];
        layer_kernel<<<F_NODES / NPB, NPB * 32>>>(src, dh, fin ? out : nullptr,
                                                  b1, b2, in_ixs, x0H, x0T, fin);
        src = dh;
    }
}

// round 16
// speedup vs baseline: 1.3957x; 1.0145x over previous
#include <cuda_runtime.h>
#include <cuda_fp16.h>

#define F_NODES 16384
#define DEG 8
#define E (F_NODES * DEG)   // 131072
#define B 64
#define H 16
#define LAYERS 10

#define NPB 8               // nodes per block = warps per block
#define TS 72               // tile row stride in halves (144B)

typedef unsigned long long u64;
typedef unsigned int u32;
typedef unsigned short u16;

// x0 fp32 for the exact final-layer residual; steady-state x traffic is fp16.
__device__ float  g_x0T[(size_t)E * B];
__device__ __half g_x0H[(size_t)E * B];
__device__ __half g_hA [(size_t)E * B];
__device__ __half g_hB [(size_t)E * B];
// fp16 hi/lo weight split (W ~= Wh + Wl to ~2^-22), built once per run.
__device__ __half g_w1h[(size_t)F_NODES * 128];
__device__ __half g_w1l[(size_t)F_NODES * 128];
__device__ __half g_w2h[(size_t)F_NODES * 128];
__device__ __half g_w2l[(size_t)F_NODES * 128];

__device__ __forceinline__ float elu1(float x) {
    float e = __expf(x) - 1.0f;
    return x > 0.0f ? x : e;
}
__device__ __forceinline__ u32 cvt2h(float lo, float hi) {
    u32 r;
    asm("cvt.rn.f16x2.f32 %0, %1, %2;" : "=r"(r) : "f"(hi), "f"(lo));
    return r;
}
__device__ __forceinline__ void mma_k8(float c[4], u32 a0, u32 a1, u32 b0) {
    asm("mma.sync.aligned.m16n8k8.row.col.f32.f16.f16.f32 "
        "{%0,%1,%2,%3}, {%4,%5}, {%6}, {%0,%1,%2,%3};"
        : "+f"(c[0]), "+f"(c[1]), "+f"(c[2]), "+f"(c[3])
        : "r"(a0), "r"(a1), "r"(b0));
}
__device__ __forceinline__ void mma_k16(float c[4], const u32 a[4], u32 b0, u32 b1) {
    asm("mma.sync.aligned.m16n8k16.row.col.f32.f16.f16.f32 "
        "{%0,%1,%2,%3}, {%4,%5,%6,%7}, {%8,%9}, {%0,%1,%2,%3};"
        : "+f"(c[0]), "+f"(c[1]), "+f"(c[2]), "+f"(c[3])
        : "r"(a[0]), "r"(a[1]), "r"(a[2]), "r"(a[3]), "r"(b0), "r"(b1));
}
__device__ __forceinline__ void ldsm4t(u32& r0, u32& r1, u32& r2, u32& r3, u32 addr) {
    asm volatile("ldmatrix.sync.aligned.m8n8.x4.trans.shared.b16 {%0,%1,%2,%3}, [%4];"
                 : "=r"(r0), "=r"(r1), "=r"(r2), "=r"(r3) : "r"(addr));
}
__device__ __forceinline__ void stsm4t(u32 addr, u32 r0, u32 r1, u32 r2, u32 r3) {
    asm volatile("stmatrix.sync.aligned.m8n8.x4.trans.shared.b16 [%0], {%1,%2,%3,%4};"
                 :: "r"(addr), "r"(r0), "r"(r1), "r"(r2), "r"(r3) : "memory");
}

// One-time fp16 hi/lo weight split.
__global__ void k_prep_weights(const float* __restrict__ W1, const float* __restrict__ W2) {
    size_t i = (size_t)blockIdx.x * blockDim.x + threadIdx.x;
    float w1 = W1[i];
    __half h1 = __float2half_rn(w1);
    g_w1h[i] = h1;
    g_w1l[i] = __float2half_rn(w1 - __half2float(h1));
    float w2 = W2[i];
    __half h2 = __float2half_rn(w2);
    g_w2h[i] = h2;
    g_w2l[i] = __float2half_rn(w2 - __half2float(h2));
}

// (B, E) row-major -> (E, B) fp32 + fp16
__global__ void k_transpose_in(const float* __restrict__ in,
                               float* __restrict__ outf, __half* __restrict__ outh) {
    __shared__ float t[32][33];
    int e0 = blockIdx.x * 32, b0 = blockIdx.y * 32;
    int tx = threadIdx.x, ty = threadIdx.y;
    t[ty][tx] = in[(size_t)(b0 + ty) * E + e0 + tx];
    __syncthreads();
    float v = t[tx][ty];
    size_t o = (size_t)(e0 + ty) * B + b0 + tx;
    outf[o] = v;
    outh[o] = __float2half(v);
}

// One GSNN layer: ONE WARP PER NODE, tensor-core MMAs, ldmatrix/stmatrix I/O.
// Weight/bias fragments loaded DIRECTLY from global (single-warp consumer, no
// reuse -> smem staging removed). All hot-loop addressing in u32 byte offsets.
__global__ __launch_bounds__(NPB * 32)
void layer_kernel(const __half* __restrict__ src, __half* __restrict__ dsth,
                  float* __restrict__ dstf,
                  const float* __restrict__ b1, const float* __restrict__ b2,
                  const int* __restrict__ in_ixs,
                  const __half* __restrict__ x0H, const float* __restrict__ x0T,
                  int final_flag) {
    __shared__ __half tiles[NPB][8 * TS];
    const int lane = threadIdx.x & 31;
    const int nl   = threadIdx.x >> 5;
    const int node = blockIdx.x * NPB + nl;
    const int t    = lane & 3;
    const int g    = lane >> 2;
    __half* tile = tiles[nl];

    // Gather columns -> smem tile G^T[d][b] (coalesced u64 loads/stores).
    const int4 ci0 = ((const int4*)(in_ixs + ((u32)node << 3)))[0];
    const int4 ci1 = ((const int4*)(in_ixs + ((u32)node << 3)))[1];
    const int cols[8] = {ci0.x, ci0.y, ci0.z, ci0.w, ci1.x, ci1.y, ci1.z, ci1.w};
    const int hw = lane >> 4;      // half-warp id
    const u32 bo8 = (u32)(lane & 15) << 3;   // byte offset within 128B column
    const char* srcb = (const char*)src;
#pragma unroll
    for (int p = 0; p < 4; p++) {
        const int d = 2 * p + hw;
        *(u64*)((char*)(tile + d * TS) + bo8) =
            *(const u64*)(srcb + (((u32)cols[d]) << 7) + bo8);
    }

    // Weight fragments direct from global (within the node's 256B lines).
    const char* w1hp = (const char*)(g_w1h + ((u32)node << 7));
    const char* w1lp = (const char*)(g_w1l + ((u32)node << 7));
    const char* w2hp = (const char*)(g_w2h + ((u32)node << 7));
    const char* w2lp = (const char*)(g_w2l + ((u32)node << 7));
    const u32 w1o = ((u32)g << 4) + ((u32)t << 2);       // (j=g row)*16B + t*4B
    u32 b1h[2], b1l[2];
    b1h[0] = *(const u32*)(w1hp + w1o);
    b1h[1] = *(const u32*)(w1hp + w1o + 128);
    b1l[0] = *(const u32*)(w1lp + w1o);
    b1l[1] = *(const u32*)(w1lp + w1o + 128);
    const u32 w2o = ((u32)g << 5) + ((u32)t << 2);       // (d=g row)*32B + t*4B
    const u32 b2h0 = *(const u32*)(w2hp + w2o);
    const u32 b2h1 = *(const u32*)(w2hp + w2o + 16);
    const u32 b2l0 = *(const u32*)(w2lp + w2o);
    const u32 b2l1 = *(const u32*)(w2lp + w2o + 16);
    // Bias fragments.
    const float2 bb1[2] = {
        *(const float2*)(b1 + ((u32)node << 4) + 2 * t),
        *(const float2*)(b1 + ((u32)node << 4) + 8 + 2 * t)
    };
    const float2 bb2 = *(const float2*)(b2 + ((u32)node << 3) + 2 * t);

    __syncwarp();

    // A fragments for GEMM1 via 2x ldmatrix.x4.trans.
    const u32 smb = (u32)__cvta_generic_to_shared(tile);
    const u32 la  = smb + (lane & 7) * (TS * 2) + (lane >> 3) * 16;
    u32 a1f[4][2];
    ldsm4t(a1f[0][0], a1f[0][1], a1f[1][0], a1f[1][1], la);
    ldsm4t(a1f[2][0], a1f[2][1], a1f[3][0], a1f[3][1], la + 64);

    // GEMM1 with bias-initialized accumulators (W hi + lo).
    float c1[4][2][4];
#pragma unroll
    for (int ni = 0; ni < 2; ni++) {
#pragma unroll
        for (int mi = 0; mi < 4; mi++) {
            c1[mi][ni][0] = bb1[ni].x; c1[mi][ni][1] = bb1[ni].y;
            c1[mi][ni][2] = bb1[ni].x; c1[mi][ni][3] = bb1[ni].y;
        }
    }
#pragma unroll
    for (int mi = 0; mi < 4; mi++) {
#pragma unroll
        for (int ni = 0; ni < 2; ni++) {
            mma_k8(c1[mi][ni], a1f[mi][0], a1f[mi][1], b1h[ni]);
            mma_k8(c1[mi][ni], a1f[mi][0], a1f[mi][1], b1l[ni]);
        }
    }

    // ELU + pack into GEMM2 A fragments (C layout == A(k16) layout).
    u32 a2f[4][4];
#pragma unroll
    for (int mi = 0; mi < 4; mi++) {
        a2f[mi][0] = cvt2h(elu1(c1[mi][0][0]), elu1(c1[mi][0][1]));
        a2f[mi][1] = cvt2h(elu1(c1[mi][0][2]), elu1(c1[mi][0][3]));
        a2f[mi][2] = cvt2h(elu1(c1[mi][1][0]), elu1(c1[mi][1][1]));
        a2f[mi][3] = cvt2h(elu1(c1[mi][1][2]), elu1(c1[mi][1][3]));
    }

    // GEMM2 with b2-initialized accumulators.
    float c2[4][4];
#pragma unroll
    for (int mi = 0; mi < 4; mi++) {
        c2[mi][0] = bb2.x; c2[mi][1] = bb2.y;
        c2[mi][2] = bb2.x; c2[mi][3] = bb2.y;
    }
#pragma unroll
    for (int mi = 0; mi < 4; mi++) {
        mma_k16(c2[mi], a2f[mi], b2h0, b2h1);
        mma_k16(c2[mi], a2f[mi], b2l0, b2l1);
    }

    if (!final_flag) {
        // C2 -> fp16 fragments -> stmatrix -> coalesced readback + residual + store.
        u32 m[8];
#pragma unroll
        for (int mi = 0; mi < 4; mi++) {
            m[2 * mi]     = cvt2h(c2[mi][0], c2[mi][1]);
            m[2 * mi + 1] = cvt2h(c2[mi][2], c2[mi][3]);
        }
        __syncwarp();   // ldsm reads of tile must complete before overwrite
        stsm4t(la, m[0], m[1], m[2], m[3]);
        stsm4t(la + 64, m[4], m[5], m[6], m[7]);
        __syncwarp();
        const u32 gb = ((u32)node << 10) + bo8;   // node*1024B + chunk
        const char* x0b = (const char*)x0H;
        char* dstb = (char*)dsth;
#pragma unroll
        for (int p = 0; p < 4; p++) {
            const int d = 2 * p + hw;
            const u64 v = *(const u64*)((char*)(tile + d * TS) + bo8);
            const u32 off = gb + ((u32)d << 7);
            const u64 r = *(const u64*)(x0b + off);
            __half2 o0 = __hadd2(((const __half2*)&v)[0], ((const __half2*)&r)[0]);
            __half2 o1 = __hadd2(((const __half2*)&v)[1], ((const __half2*)&r)[1]);
            u64 ov;
            ((__half2*)&ov)[0] = o0;
            ((__half2*)&ov)[1] = o1;
            *(u64*)(dstb + off) = ov;
        }
    } else {
        // Final layer: exact fp32 residual, fp32 (B,E) output (register scatter).
#pragma unroll
        for (int mi = 0; mi < 4; mi++) {
#pragma unroll
            for (int e = 0; e < 4; e++) {
                const int bb = 16 * mi + g + ((e >> 1) << 3);
                const int d  = 2 * t + (e & 1);
                const float rv = x0T[((u32)node << 9) + ((u32)d << 6) + bb];
                dstf[(size_t)bb * E + ((u32)node << 3) + d] = c2[mi][e] + rv;
            }
        }
    }
}

extern "C" void kernel_launch(void* const* d_in, const int* in_sizes, int n_in,
                              void* d_out, int out_size) {
    const float* x0     = (const float*)d_in[0];
    const float* W1     = (const float*)d_in[1];
    const float* b1     = (const float*)d_in[2];
    const float* W2     = (const float*)d_in[3];
    const float* b2     = (const float*)d_in[4];
    const int*   in_ixs = (const int*)d_in[5];
    float* out = (float*)d_out;

    float *x0T;
    __half *x0H, *hA, *hB;
    cudaGetSymbolAddress((void**)&x0T, g_x0T);
    cudaGetSymbolAddress((void**)&x0H, g_x0H);
    cudaGetSymbolAddress((void**)&hA,  g_hA);
    cudaGetSymbolAddress((void**)&hB,  g_hB);

    k_prep_weights<<<(F_NODES * 128) / 256, 256>>>(W1, W2);
    k_transpose_in<<<dim3(E / 32, B / 32), dim3(32, 32)>>>(x0, x0T, x0H);

    const __half* src = x0H;
    __half* bufs[2] = {hA, hB};
    for (int L = 0; L < LAYERS; L++) {
        const int fin = (L == LAYERS - 1);
        __half* dh = fin ? nullptr : bufs[L & 1];
        layer_kernel<<<F_NODES / NPB, NPB * 32>>>(src, dh, fin ? out : nullptr,
                                                  b1, b2, in_ixs, x0H, x0T, fin);
        src = dh;
    }
}

// round 17
// speedup vs baseline: 1.4288x; 1.0237x over previous
#include <cuda_runtime.h>
#include <cuda_fp16.h>

#define F_NODES 16384
#define DEG 8
#define E (F_NODES * DEG)   // 131072
#define B 64
#define H 16
#define LAYERS 10

#define NPB 8               // nodes per block = warps per block
#define TS 72               // tile row stride in halves (144B)

typedef unsigned long long u64;
typedef unsigned int u32;
typedef unsigned short u16;

// x0 fp32 for the exact final-layer residual; steady-state x traffic is fp16.
__device__ float  g_x0T[(size_t)E * B];
__device__ __half g_x0H[(size_t)E * B];
__device__ __half g_hA [(size_t)E * B];
__device__ __half g_hB [(size_t)E * B];
// Fragment-ready packed weights: u64 = (lo-split word << 32) | hi-split word.
// w1p[node*64 + j*4 + t]  : halves W1[node][j][2t..2t+1]   (hi and lo split)
// w2p[node*64 + g*8 + k]  : halves W2[node][g][2k..2k+1]
__device__ u64    g_w1p[(size_t)F_NODES * 64];
__device__ u64    g_w2p[(size_t)F_NODES * 64];
__device__ float4 g_b1p[(size_t)F_NODES * 4];   // (b1[2t], b1[2t+1], b1[8+2t], b1[8+2t+1])

__device__ __forceinline__ float elu1(float x) {
    float e = __expf(x) - 1.0f;
    return x > 0.0f ? x : e;
}
__device__ __forceinline__ u32 cvt2h(float lo, float hi) {
    u32 r;
    asm("cvt.rn.f16x2.f32 %0, %1, %2;" : "=r"(r) : "f"(hi), "f"(lo));
    return r;
}
__device__ __forceinline__ void mma_k8(float c[4], u32 a0, u32 a1, u32 b0) {
    asm("mma.sync.aligned.m16n8k8.row.col.f32.f16.f16.f32 "
        "{%0,%1,%2,%3}, {%4,%5}, {%6}, {%0,%1,%2,%3};"
        : "+f"(c[0]), "+f"(c[1]), "+f"(c[2]), "+f"(c[3])
        : "r"(a0), "r"(a1), "r"(b0));
}
__device__ __forceinline__ void mma_k16(float c[4], const u32 a[4], u32 b0, u32 b1) {
    asm("mma.sync.aligned.m16n8k16.row.col.f32.f16.f16.f32 "
        "{%0,%1,%2,%3}, {%4,%5,%6,%7}, {%8,%9}, {%0,%1,%2,%3};"
        : "+f"(c[0]), "+f"(c[1]), "+f"(c[2]), "+f"(c[3])
        : "r"(a[0]), "r"(a[1]), "r"(a[2]), "r"(a[3]), "r"(b0), "r"(b1));
}
__device__ __forceinline__ void ldsm4t(u32& r0, u32& r1, u32& r2, u32& r3, u32 addr) {
    asm volatile("ldmatrix.sync.aligned.m8n8.x4.trans.shared.b16 {%0,%1,%2,%3}, [%4];"
                 : "=r"(r0), "=r"(r1), "=r"(r2), "=r"(r3) : "r"(addr));
}
__device__ __forceinline__ void stsm4t(u32 addr, u32 r0, u32 r1, u32 r2, u32 r3) {
    asm volatile("stmatrix.sync.aligned.m8n8.x4.trans.shared.b16 [%0], {%1,%2,%3,%4};"
                 :: "r"(addr), "r"(r0), "r"(r1), "r"(r2), "r"(r3) : "memory");
}
__device__ __forceinline__ u64 split2(float w0, float w1) {
    __half h0 = __float2half_rn(w0), h1 = __float2half_rn(w1);
    __half l0 = __float2half_rn(w0 - __half2float(h0));
    __half l1 = __float2half_rn(w1 - __half2float(h1));
    u32 hiw = ((u32)__half_as_ushort(h1) << 16) | __half_as_ushort(h0);
    u32 low = ((u32)__half_as_ushort(l1) << 16) | __half_as_ushort(l0);
    return ((u64)low << 32) | hiw;
}

// One-time fragment-ready weight packing.
__global__ void k_prep_w(const float* __restrict__ W1, const float* __restrict__ W2) {
    u32 i = blockIdx.x * blockDim.x + threadIdx.x;   // < F_NODES*64
    const u32 node = i >> 6, r = i & 63;
    {
        const u32 j = r >> 2, t = r & 3;
        const float* p = W1 + (size_t)node * 128 + j * 8 + 2 * t;
        g_w1p[i] = split2(p[0], p[1]);
    }
    {
        const u32 g = r >> 3, k = r & 7;
        const float* p = W2 + (size_t)node * 128 + g * 16 + 2 * k;
        g_w2p[i] = split2(p[0], p[1]);
    }
}
__global__ void k_prep_b1(const float* __restrict__ b1) {
    u32 i = blockIdx.x * blockDim.x + threadIdx.x;   // < F_NODES*4
    const u32 node = i >> 2, t = i & 3;
    const float* p = b1 + (size_t)node * 16;
    g_b1p[i] = make_float4(p[2 * t], p[2 * t + 1], p[8 + 2 * t], p[8 + 2 * t + 1]);
}

// (B, E) row-major -> (E, B) fp32 + fp16
__global__ void k_transpose_in(const float* __restrict__ in,
                               float* __restrict__ outf, __half* __restrict__ outh) {
    __shared__ float t[32][33];
    int e0 = blockIdx.x * 32, b0 = blockIdx.y * 32;
    int tx = threadIdx.x, ty = threadIdx.y;
    t[ty][tx] = in[(size_t)(b0 + ty) * E + e0 + tx];
    __syncthreads();
    float v = t[tx][ty];
    size_t o = (size_t)(e0 + ty) * B + b0 + tx;
    outf[o] = v;
    outh[o] = __float2half(v);
}

// One GSNN layer: ONE WARP PER NODE, tensor-core MMAs, ldmatrix/stmatrix I/O.
// ALL global reads (gather, residual, weights, biases) issued up front.
__global__ __launch_bounds__(NPB * 32)
void layer_kernel(const __half* __restrict__ src, __half* __restrict__ dsth,
                  float* __restrict__ dstf,
                  const float* __restrict__ b2,
                  const int* __restrict__ in_ixs,
                  const __half* __restrict__ x0H, const float* __restrict__ x0T,
                  int final_flag) {
    __shared__ __half tiles[NPB][8 * TS];
    const int lane = threadIdx.x & 31;
    const int nl   = threadIdx.x >> 5;
    const int node = blockIdx.x * NPB + nl;
    const int t    = lane & 3;
    const int g    = lane >> 2;
    __half* tile = tiles[nl];

    // ---- Issue every global load up front (max MLP per warp) ----
    const int4 ci0 = ((const int4*)(in_ixs + ((u32)node << 3)))[0];
    const int4 ci1 = ((const int4*)(in_ixs + ((u32)node << 3)))[1];
    const int cols[8] = {ci0.x, ci0.y, ci0.z, ci0.w, ci1.x, ci1.y, ci1.z, ci1.w};
    const int hw = lane >> 4;
    const u32 bo8 = (u32)(lane & 15) << 3;
    const char* srcb = (const char*)src;

    u64 gv[4];
#pragma unroll
    for (int p = 0; p < 4; p++)
        gv[p] = *(const u64*)(srcb + (((u32)cols[2 * p + hw]) << 7) + bo8);

    // Residual prefetch (hidden under the MMA phase).
    const u32 gb = ((u32)node << 10) + bo8;
    u64 rres[4];
    if (!final_flag) {
        const char* x0b = (const char*)x0H;
#pragma unroll
        for (int p = 0; p < 4; p++)
            rres[p] = *(const u64*)(x0b + gb + ((u32)(2 * p + hw) << 7));
    }

    // Fragment-ready weights: 4x LDG.64 total.
    const u64* w1p = g_w1p + ((u32)node << 6);
    const u64* w2p = g_w2p + ((u32)node << 6);
    const u64 wa = w1p[(g << 2) + t];
    const u64 wb = w1p[((g + 8) << 2) + t];
    const u64 wc = w2p[(g << 3) + t];
    const u64 wd = w2p[(g << 3) + t + 4];
    const float4 bb1v = g_b1p[((u32)node << 2) + t];
    const float2 bb2 = *(const float2*)(b2 + ((u32)node << 3) + 2 * t);

    const u32 b1h[2] = {(u32)wa, (u32)wb};
    const u32 b1l[2] = {(u32)(wa >> 32), (u32)(wb >> 32)};
    const u32 b2h0 = (u32)wc, b2l0 = (u32)(wc >> 32);
    const u32 b2h1 = (u32)wd, b2l1 = (u32)(wd >> 32);

    // ---- Stage gathered columns into smem tile, build A fragments ----
#pragma unroll
    for (int p = 0; p < 4; p++)
        *(u64*)((char*)(tile + (2 * p + hw) * TS) + bo8) = gv[p];
    __syncwarp();

    const u32 smb = (u32)__cvta_generic_to_shared(tile);
    const u32 la  = smb + (lane & 7) * (TS * 2) + (lane >> 3) * 16;
    u32 a1f[4][2];
    ldsm4t(a1f[0][0], a1f[0][1], a1f[1][0], a1f[1][1], la);
    ldsm4t(a1f[2][0], a1f[2][1], a1f[3][0], a1f[3][1], la + 64);

    // ---- GEMM1 (W hi + lo), bias-initialized ----
    float c1[4][2][4];
#pragma unroll
    for (int mi = 0; mi < 4; mi++) {
        c1[mi][0][0] = bb1v.x; c1[mi][0][1] = bb1v.y;
        c1[mi][0][2] = bb1v.x; c1[mi][0][3] = bb1v.y;
        c1[mi][1][0] = bb1v.z; c1[mi][1][1] = bb1v.w;
        c1[mi][1][2] = bb1v.z; c1[mi][1][3] = bb1v.w;
    }
#pragma unroll
    for (int mi = 0; mi < 4; mi++) {
#pragma unroll
        for (int ni = 0; ni < 2; ni++) {
            mma_k8(c1[mi][ni], a1f[mi][0], a1f[mi][1], b1h[ni]);
            mma_k8(c1[mi][ni], a1f[mi][0], a1f[mi][1], b1l[ni]);
        }
    }

    // ---- ELU + pack GEMM2 A fragments ----
    u32 a2f[4][4];
#pragma unroll
    for (int mi = 0; mi < 4; mi++) {
        a2f[mi][0] = cvt2h(elu1(c1[mi][0][0]), elu1(c1[mi][0][1]));
        a2f[mi][1] = cvt2h(elu1(c1[mi][0][2]), elu1(c1[mi][0][3]));
        a2f[mi][2] = cvt2h(elu1(c1[mi][1][0]), elu1(c1[mi][1][1]));
        a2f[mi][3] = cvt2h(elu1(c1[mi][1][2]), elu1(c1[mi][1][3]));
    }

    // ---- GEMM2 (W hi + lo), b2-initialized ----
    float c2[4][4];
#pragma unroll
    for (int mi = 0; mi < 4; mi++) {
        c2[mi][0] = bb2.x; c2[mi][1] = bb2.y;
        c2[mi][2] = bb2.x; c2[mi][3] = bb2.y;
    }
#pragma unroll
    for (int mi = 0; mi < 4; mi++) {
        mma_k16(c2[mi], a2f[mi], b2h0, b2h1);
        mma_k16(c2[mi], a2f[mi], b2l0, b2l1);
    }

    if (!final_flag) {
        // C2 -> fp16 -> stmatrix -> coalesced readback + prefetched residual.
        u32 m[8];
#pragma unroll
        for (int mi = 0; mi < 4; mi++) {
            m[2 * mi]     = cvt2h(c2[mi][0], c2[mi][1]);
            m[2 * mi + 1] = cvt2h(c2[mi][2], c2[mi][3]);
        }
        __syncwarp();
        stsm4t(la, m[0], m[1], m[2], m[3]);
        stsm4t(la + 64, m[4], m[5], m[6], m[7]);
        __syncwarp();
        char* dstb = (char*)dsth;
#pragma unroll
        for (int p = 0; p < 4; p++) {
            const int d = 2 * p + hw;
            const u64 v = *(const u64*)((char*)(tile + d * TS) + bo8);
            __half2 o0 = __hadd2(((const __half2*)&v)[0], ((const __half2*)&rres[p])[0]);
            __half2 o1 = __hadd2(((const __half2*)&v)[1], ((const __half2*)&rres[p])[1]);
            u64 ov;
            ((__half2*)&ov)[0] = o0;
            ((__half2*)&ov)[1] = o1;
            *(u64*)(dstb + gb + ((u32)d << 7)) = ov;
        }
    } else {
        // Final layer: exact fp32 residual, fp32 (B,E) output (register scatter).
#pragma unroll
        for (int mi = 0; mi < 4; mi++) {
#pragma unroll
            for (int e = 0; e < 4; e++) {
                const int bb = 16 * mi + g + ((e >> 1) << 3);
                const int d  = 2 * t + (e & 1);
                const float rv = x0T[((u32)node << 9) + ((u32)d << 6) + bb];
                dstf[(size_t)bb * E + ((u32)node << 3) + d] = c2[mi][e] + rv;
            }
        }
    }
}

extern "C" void kernel_launch(void* const* d_in, const int* in_sizes, int n_in,
                              void* d_out, int out_size) {
    const float* x0     = (const float*)d_in[0];
    const float* W1     = (const float*)d_in[1];
    const float* b1     = (const float*)d_in[2];
    const float* W2     = (const float*)d_in[3];
    const float* b2     = (const float*)d_in[4];
    const int*   in_ixs = (const int*)d_in[5];
    float* out = (float*)d_out;

    float *x0T;
    __half *x0H, *hA, *hB;
    cudaGetSymbolAddress((void**)&x0T, g_x0T);
    cudaGetSymbolAddress((void**)&x0H, g_x0H);
    cudaGetSymbolAddress((void**)&hA,  g_hA);
    cudaGetSymbolAddress((void**)&hB,  g_hB);

    k_prep_w<<<(F_NODES * 64) / 256, 256>>>(W1, W2);
    k_prep_b1<<<(F_NODES * 4) / 256, 256>>>(b1);
    k_transpose_in<<<dim3(E / 32, B / 32), dim3(32, 32)>>>(x0, x0T, x0H);

    const __half* src = x0H;
    __half* bufs[2] = {hA, hB};
    for (int L = 0; L < LAYERS; L++) {
        const int fin = (L == LAYERS - 1);
        __half* dh = fin ? nullptr : bufs[L & 1];
        layer_kernel<<<F_NODES / NPB, NPB * 32>>>(src, dh, fin ? out : nullptr,
                                                  b2, in_ixs, x0H, x0T, fin);
        src = dh;
    }
}